// round 1
// baseline (speedup 1.0000x reference)
#include <cuda_runtime.h>

#define NB 16
#define NL 1024
#define NH 8
#define NE 64
#define NM 64
#define NBH (NB*NH)
#define HE 512                       // NH*NE
#define SCALE_F 3.814697265625e-06f  // 1/(512*512)

// -------- scratch (static device globals; no runtime allocation) --------
static __device__ float  g_Mbuf[NBH*NE*NE];      // [bh][e][o] = sum_s k_e v_o
static __device__ float  g_ksum[NBH*NE];
static __device__ float  g_vsum[NBH*NE];
static __device__ float4 g_X[(NBH*NE*NM)/2];     // float2 (Xr,Xi) [bh][e][m]
static __device__ float4 g_Y[(NBH*NE*NM)/2];     // float2 (Yr,Yi) [bh][o][m], pre-scaled c_m/2048

// ===================== kernel A: k/v stats (M, ksum, vsum) =====================
__global__ void __launch_bounds__(256) k_stats(const float* __restrict__ kin,
                                               const float* __restrict__ vin) {
    const int bh = blockIdx.x;
    const int b = bh >> 3, h = bh & 7;
    const int t = threadIdx.x;
    __shared__ float sk[8][NE];
    __shared__ float sv[8][NE];
    const int e0 = (t >> 4) << 2;
    const int d0 = (t & 15) << 2;
    float acc[4][4] = {};
    float ka = 0.f, va = 0.f;
    const int base = b * NL * HE + h * NE;
    for (int s0 = 0; s0 < NL; s0 += 8) {
        __syncthreads();
        #pragma unroll
        for (int r = 0; r < 2; ++r) {
            int idx = r * 256 + t;
            int ss = idx >> 6, e = idx & 63;
            int g = base + (s0 + ss) * HE + e;
            sk[ss][e] = kin[g];
            sv[ss][e] = vin[g];
        }
        __syncthreads();
        #pragma unroll
        for (int ss = 0; ss < 8; ++ss) {
            float kr[4], vr[4];
            #pragma unroll
            for (int i = 0; i < 4; ++i) { kr[i] = sk[ss][e0+i]; vr[i] = sv[ss][d0+i]; }
            #pragma unroll
            for (int i = 0; i < 4; ++i)
                #pragma unroll
                for (int j = 0; j < 4; ++j)
                    acc[i][j] = fmaf(kr[i], vr[j], acc[i][j]);
        }
        if (t < 64) {
            #pragma unroll
            for (int ss = 0; ss < 8; ++ss) { ka += sk[ss][t]; va += sv[ss][t]; }
        }
    }
    float* Mo = g_Mbuf + bh * (NE*NE);
    #pragma unroll
    for (int i = 0; i < 4; ++i)
        #pragma unroll
        for (int j = 0; j < 4; ++j)
            Mo[(e0+i)*NE + d0 + j] = acc[i][j];
    if (t < 64) { g_ksum[bh*NE + t] = ka; g_vsum[bh*NE + t] = va; }
}

// ===================== kernel B: forward truncated DFT of q =====================
// X[e,m] = sum_l q[l,e] * exp(-2*pi*i*m*l/1024), m = 0..63
__global__ void __launch_bounds__(256) k_fdft(const float* __restrict__ q) {
    const int bh = blockIdx.x;
    const int b = bh >> 3, h = bh & 7;
    const int t = threadIdx.x;
    __shared__ float sq[64][NE];
    __shared__ float2 stw[1024];
    for (int j = t; j < 1024; j += 256) {
        float s, c;
        sincospif((float)j * (1.0f/512.0f), &s, &c);   // angle = 2*pi*j/1024
        stw[j] = make_float2(c, s);
    }
    const int e0 = (t >> 4) << 2;
    const int m0 = blockIdx.y * 32 + ((t & 15) << 1);
    float xr[4][2] = {}, xi[4][2] = {};
    int jj[2] = {0, 0};                                // jj[mm] = (m*l) mod 1024
    const int base = b * NL * HE + h * NE;
    for (int l0 = 0; l0 < NL; l0 += 64) {
        __syncthreads();
        const float4* qg = (const float4*)(q + base + l0 * HE);
        #pragma unroll
        for (int r = 0; r < 4; ++r) {
            int f = r * 256 + t;
            int row = f >> 4, c4 = f & 15;
            ((float4*)sq)[row*16 + c4] = qg[row*128 + c4];
        }
        __syncthreads();
        #pragma unroll 4
        for (int l = 0; l < 64; ++l) {
            float4 qv = *(const float4*)&sq[l][e0];
            #pragma unroll
            for (int mm = 0; mm < 2; ++mm) {
                float2 cs = stw[jj[mm]];
                jj[mm] = (jj[mm] + m0 + mm) & 1023;
                xr[0][mm] = fmaf(qv.x,  cs.x, xr[0][mm]);
                xi[0][mm] = fmaf(qv.x, -cs.y, xi[0][mm]);
                xr[1][mm] = fmaf(qv.y,  cs.x, xr[1][mm]);
                xi[1][mm] = fmaf(qv.y, -cs.y, xi[1][mm]);
                xr[2][mm] = fmaf(qv.z,  cs.x, xr[2][mm]);
                xi[2][mm] = fmaf(qv.z, -cs.y, xi[2][mm]);
                xr[3][mm] = fmaf(qv.w,  cs.x, xr[3][mm]);
                xi[3][mm] = fmaf(qv.w, -cs.y, xi[3][mm]);
            }
        }
    }
    float2* Xo = ((float2*)g_X) + bh * (NE*NM);
    #pragma unroll
    for (int i = 0; i < 4; ++i)
        #pragma unroll
        for (int mm = 0; mm < 2; ++mm)
            Xo[(e0+i)*NM + m0 + mm] = make_float2(xr[i][mm], xi[i][mm]);
}

// ===================== kernel C: per-mode complex mix Y = X * W =====================
// Y[o,m] = sum_i X[i,m] * W[h,i,o,m]; stored pre-scaled by c_m/2048 (c_0=1 else 2, folds
// irfft 1/1024 normalization and the final /2).
__global__ void __launch_bounds__(512) k_mix(const float* __restrict__ wre,
                                             const float* __restrict__ wim) {
    const int h  = blockIdx.x >> 4;
    const int m0 = (blockIdx.x & 15) << 2;
    const int t = threadIdx.x;
    const int b  = t >> 5;
    const int o0 = (t & 31) << 1;
    const int bh = b * NH + h;
    float yr[2][4] = {}, yi[2][4] = {};
    const float2* Xb = ((const float2*)g_X) + bh * (NE*NM);
    for (int i = 0; i < NE; ++i) {
        const float4* xp = (const float4*)(Xb + i*NM + m0);
        float4 x01 = xp[0];
        float4 x23 = xp[1];
        float xre[4] = {x01.x, x01.z, x23.x, x23.z};
        float xim[4] = {x01.y, x01.w, x23.y, x23.w};
        #pragma unroll
        for (int oo = 0; oo < 2; ++oo) {
            int wbase = ((h*NE + i)*NE + (o0+oo))*NM + m0;
            float4 wr = *(const float4*)(wre + wbase);
            float4 wi = *(const float4*)(wim + wbase);
            float wrv[4] = {wr.x, wr.y, wr.z, wr.w};
            float wiv[4] = {wi.x, wi.y, wi.z, wi.w};
            #pragma unroll
            for (int mm = 0; mm < 4; ++mm) {
                yr[oo][mm] = fmaf( xre[mm], wrv[mm], yr[oo][mm]);
                yr[oo][mm] = fmaf(-xim[mm], wiv[mm], yr[oo][mm]);
                yi[oo][mm] = fmaf( xre[mm], wiv[mm], yi[oo][mm]);
                yi[oo][mm] = fmaf( xim[mm], wrv[mm], yi[oo][mm]);
            }
        }
    }
    float2* Yo = ((float2*)g_Y) + bh * (NE*NM);
    #pragma unroll
    for (int oo = 0; oo < 2; ++oo)
        #pragma unroll
        for (int mm = 0; mm < 4; ++mm) {
            int m = m0 + mm;
            float f = (m == 0 ? 1.0f : 2.0f) * (1.0f / 2048.0f);
            Yo[(o0+oo)*NM + m] = make_float2(yr[oo][mm]*f, yi[oo][mm]*f);
        }
}

// ===================== kernel D1: linearized local-attention half =====================
// out = 0.5 * (vsum[o] + SCALE * sum_e q[l,e]*M[e,o]) / (1024 + SCALE * q[l,:].ksum)
__global__ void __launch_bounds__(256) k_local(const float* __restrict__ q,
                                               float* __restrict__ out) {
    const int bh = blockIdx.x;
    const int b = bh >> 3, h = bh & 7;
    const int t = threadIdx.x;
    __shared__ float sM[NE*NE];
    __shared__ float sq[64][NE];
    __shared__ float sks[NE];
    __shared__ float svs[NE];
    const float* Mi = g_Mbuf + bh*(NE*NE);
    for (int idx = t; idx < NE*NE; idx += 256) sM[idx] = Mi[idx];
    if (t < NE) { sks[t] = g_ksum[bh*NE+t]; svs[t] = g_vsum[bh*NE+t]; }
    const int og = t & 15, lg = t >> 4;
    const int o0 = og << 2;
    const int base  = b * NL * HE + h * NE;
    const int lbase = blockIdx.y * 512;
    for (int l0 = lbase; l0 < lbase + 512; l0 += 64) {
        __syncthreads();
        const float4* qg = (const float4*)(q + base + l0*HE);
        #pragma unroll
        for (int r = 0; r < 4; ++r) {
            int f = r*256 + t;
            int row = f >> 4, c4 = f & 15;
            ((float4*)sq)[row*16+c4] = qg[row*128 + c4];
        }
        __syncthreads();
        float acc[4][4] = {};
        float z[4] = {};
        #pragma unroll 4
        for (int e = 0; e < NE; ++e) {
            float ks = sks[e];
            float4 mv = *(const float4*)&sM[e*NE + o0];
            #pragma unroll
            for (int ll = 0; ll < 4; ++ll) {
                float qv = sq[lg*4+ll][e];
                z[ll]      = fmaf(qv, ks,   z[ll]);
                acc[ll][0] = fmaf(qv, mv.x, acc[ll][0]);
                acc[ll][1] = fmaf(qv, mv.y, acc[ll][1]);
                acc[ll][2] = fmaf(qv, mv.z, acc[ll][2]);
                acc[ll][3] = fmaf(qv, mv.w, acc[ll][3]);
            }
        }
        #pragma unroll
        for (int ll = 0; ll < 4; ++ll) {
            int l = l0 + lg*4 + ll;
            float Z = 1024.0f + SCALE_F * z[ll];
            float inv = 0.5f / Z;
            float4 ov;
            ov.x = (svs[o0+0] + SCALE_F*acc[ll][0]) * inv;
            ov.y = (svs[o0+1] + SCALE_F*acc[ll][1]) * inv;
            ov.z = (svs[o0+2] + SCALE_F*acc[ll][2]) * inv;
            ov.w = (svs[o0+3] + SCALE_F*acc[ll][3]) * inv;
            *(float4*)(out + (b*NL + l)*HE + h*NE + o0) = ov;
        }
    }
}

// ===================== kernel D2: inverse truncated DFT, add to out =====================
// out[l,o] += sum_m (Yr'[o,m]*cos(theta) - Yi'[o,m]*sin(theta)), theta = 2*pi*m*l/1024
__global__ void __launch_bounds__(256) k_spec(float* __restrict__ out) {
    const int bh = blockIdx.x;
    const int b = bh >> 3, h = bh & 7;
    const int t = threadIdx.x;
    __shared__ float sYr[64*68];
    __shared__ float sYi[64*68];
    __shared__ float2 stw[1024];
    for (int j = t; j < 1024; j += 256) {
        float s, c;
        sincospif((float)j * (1.0f/512.0f), &s, &c);
        stw[j] = make_float2(c, s);
    }
    const float2* Yb = ((const float2*)g_Y) + bh*(NE*NM);
    for (int idx = t; idx < NE*NM; idx += 256) {
        int o = idx >> 6, m = idx & 63;
        float2 yv = Yb[idx];
        sYr[m*68 + o] = yv.x;
        sYi[m*68 + o] = yv.y;
    }
    __syncthreads();
    const int og = t & 15, lg = t >> 4;
    const int o0 = og << 2;
    const int lbase = blockIdx.y * 512;
    for (int l0 = lbase; l0 < lbase + 512; l0 += 64) {
        float acc[4][4] = {};
        int lglob[4], jj[4];
        #pragma unroll
        for (int ll = 0; ll < 4; ++ll) { lglob[ll] = l0 + lg*4 + ll; jj[ll] = 0; }
        #pragma unroll 2
        for (int m = 0; m < NM; ++m) {
            float4 yrv = *(const float4*)&sYr[m*68 + o0];
            float4 yiv = *(const float4*)&sYi[m*68 + o0];
            #pragma unroll
            for (int ll = 0; ll < 4; ++ll) {
                float2 cs = stw[jj[ll]];
                jj[ll] = (jj[ll] + lglob[ll]) & 1023;
                acc[ll][0] = fmaf(yrv.x,  cs.x, acc[ll][0]);
                acc[ll][0] = fmaf(yiv.x, -cs.y, acc[ll][0]);
                acc[ll][1] = fmaf(yrv.y,  cs.x, acc[ll][1]);
                acc[ll][1] = fmaf(yiv.y, -cs.y, acc[ll][1]);
                acc[ll][2] = fmaf(yrv.z,  cs.x, acc[ll][2]);
                acc[ll][2] = fmaf(yiv.z, -cs.y, acc[ll][2]);
                acc[ll][3] = fmaf(yrv.w,  cs.x, acc[ll][3]);
                acc[ll][3] = fmaf(yiv.w, -cs.y, acc[ll][3]);
            }
        }
        #pragma unroll
        for (int ll = 0; ll < 4; ++ll) {
            float* op = out + (b*NL + lglob[ll])*HE + h*NE + o0;
            float4 cur = *(const float4*)op;
            cur.x += acc[ll][0];
            cur.y += acc[ll][1];
            cur.z += acc[ll][2];
            cur.w += acc[ll][3];
            *(float4*)op = cur;
        }
    }
}

// ===================== launch =====================
extern "C" void kernel_launch(void* const* d_in, const int* in_sizes, int n_in,
                              void* d_out, int out_size) {
    (void)in_sizes; (void)n_in; (void)out_size;
    const float* q   = (const float*)d_in[0];
    const float* k   = (const float*)d_in[1];
    const float* v   = (const float*)d_in[2];
    // d_in[3] = mask (present -> reference applies no masking); unused
    const float* wre = (const float*)d_in[4];
    const float* wim = (const float*)d_in[5];
    float* out = (float*)d_out;

    k_stats<<<NBH, 256>>>(k, v);
    k_fdft <<<dim3(NBH, 2), 256>>>(q);
    k_mix  <<<128, 512>>>(wre, wim);
    k_local<<<dim3(NBH, 2), 256>>>(q, out);
    k_spec <<<dim3(NBH, 2), 256>>>(out);
}